// round 3
// baseline (speedup 1.0000x reference)
#include <cuda_runtime.h>
#include <cstdint>
#include <cstddef>

#define DEVI static __device__ __forceinline__

namespace li {

constexpr int B = 32, T = 1024, IN = 1024, OUT = 1024;
constexpr int TT = 128;                  // time rows per tile (GEMM M)
constexpr int TO = 128;                  // out cols per CTA   (GEMM N)
constexpr int BK = 32;                   // fp32 per K slab (= one 128B row)
constexpr int SLABS = IN / BK;           // 32
constexpr int TILES = T / TT;            // 8
constexpr int STAGES = 4;

constexpr int STAGE_BYTES = (TT + TO) * BK * 4;          // 32 KB (X 16K + W 16K)
constexpr int STG_STRIDE = 132;                          // padded floats
constexpr int STAGING_OFF_F = STAGES * STAGE_BYTES / 4;  // float offset
constexpr int SMEM_DYN = STAGES * STAGE_BYTES + TT * STG_STRIDE * 4;  // 198656

DEVI uint32_t s2u(const void* p) {
  uint32_t a;
  asm("{ .reg .u64 t; cvta.to.shared.u64 t, %1; cvt.u32.u64 %0, t; }"
      : "=r"(a) : "l"(p));
  return a;
}

DEVI void cp16(uint32_t s, const void* g) {
  asm volatile("cp.async.cg.shared.global [%0], [%1], 16;" :: "r"(s), "l"(g)
               : "memory");
}
DEVI void cp_commit() { asm volatile("cp.async.commit_group;" ::: "memory"); }
DEVI void cp_wait2() { asm volatile("cp.async.wait_group 2;" ::: "memory"); }

DEVI void ldsm4(uint32_t* r, uint32_t a) {
  asm volatile("ldmatrix.sync.aligned.m8n8.x4.shared.b16 {%0,%1,%2,%3}, [%4];"
               : "=r"(r[0]), "=r"(r[1]), "=r"(r[2]), "=r"(r[3]) : "r"(a));
}
DEVI void ldsm2(uint32_t* r, uint32_t a) {
  asm volatile("ldmatrix.sync.aligned.m8n8.x2.shared.b16 {%0,%1}, [%2];"
               : "=r"(r[0]), "=r"(r[1]) : "r"(a));
}
DEVI void mma8(float* c, const uint32_t* a, const uint32_t* b) {
  asm volatile(
      "mma.sync.aligned.m16n8k8.row.col.f32.tf32.tf32.f32 "
      "{%0,%1,%2,%3}, {%4,%5,%6,%7}, {%8,%9}, {%0,%1,%2,%3};"
      : "+f"(c[0]), "+f"(c[1]), "+f"(c[2]), "+f"(c[3])
      : "r"(a[0]), "r"(a[1]), "r"(a[2]), "r"(a[3]), "r"(b[0]), "r"(b[1]));
}
// round-to-nearest tf32: add half-ulp (bit 12) of the 13 truncated mantissa bits
DEVI uint32_t rn_tf32(uint32_t x) { return x + 0x1000u; }

__global__ void __launch_bounds__(256, 1)
li_kernel(const float* __restrict__ X, const float* __restrict__ W,
          const float* __restrict__ bias, const float* __restrict__ decay,
          float* __restrict__ out) {
  extern __shared__ float dsm[];
  const uint32_t sbase = s2u(dsm);
  float* staging = dsm + STAGING_OFF_F;

  const int tid = threadIdx.x;
  const int wid = tid >> 5;
  const int lane = tid & 31;
  const int bb = blockIdx.x >> 3;
  const int o0 = (blockIdx.x & 7) * TO;

  // ---- scan state (threads 0..127 own one o-channel) ----
  float dcy = 0.f, omd = 0.f, bo = 0.f, u = 0.f;
  if (tid < 128) {
    dcy = decay[o0 + tid];
    omd = 1.0f - dcy;
    bo = bias[o0 + tid];
  }

  // ---- cp.async per-thread constants ----
  const int lr = tid >> 3;                         // row 0..31 (+32*i)
  const int lc = tid & 7;                          // 16B chunk 0..7
  const uint32_t sw_off =
      (uint32_t)lr * 128 + (uint32_t)((lc ^ (lr & 7)) << 4);
  const float* Wg = W + (size_t)(o0 + lr) * IN + lc * 4;

  // ---- mma per-thread address constants ----
  const int warp_m = wid >> 2, warp_n = wid & 3;
  const int l7 = lane & 7;
  const int rowA = warp_m * 64 + ((lane >> 3) & 1) * 8 + l7;
  const int hiA = lane >> 4;
  const uint32_t aRow = (uint32_t)rowA * 128;
  const int rowB = warp_n * 32 + l7;
  const int hiB = (lane >> 3) & 1;
  const uint32_t bRow = (uint32_t)(TT * BK * 4) + (uint32_t)rowB * 128;

  float acc[4][4][4];

  auto load_slab = [&](int t0, int slab, int s) {
    const float* Xg = X + (size_t)(bb * T + t0 + lr) * IN + slab * BK + lc * 4;
    const float* Ws = Wg + slab * BK;
    const uint32_t sb = sbase + (uint32_t)s * STAGE_BYTES;
#pragma unroll
    for (int i = 0; i < 4; ++i)
      cp16(sb + sw_off + (uint32_t)i * 4096, Xg + (size_t)i * 32 * IN);
#pragma unroll
    for (int i = 0; i < 4; ++i)
      cp16(sb + (uint32_t)(TT * BK * 4) + sw_off + (uint32_t)i * 4096,
           Ws + (size_t)i * 32 * IN);
  };

  // prologue: slabs 0..2 of tile 0
  load_slab(0, 0, 0); cp_commit();
  load_slab(0, 1, 1); cp_commit();
  load_slab(0, 2, 2); cp_commit();

  for (int i = 0; i < TILES; ++i) {
    const int t0 = i * TT;
#pragma unroll
    for (int mf = 0; mf < 4; ++mf)
#pragma unroll
      for (int nf = 0; nf < 4; ++nf)
#pragma unroll
        for (int j = 0; j < 4; ++j) acc[mf][nf][j] = 0.f;

    for (int ks = 0; ks < SLABS; ++ks) {
      cp_wait2();
      __syncthreads();
      const int nk = ks + STAGES - 1;
      if (nk < SLABS)
        load_slab(t0, nk, nk & 3);
      else if (i + 1 < TILES)
        load_slab(t0 + TT, nk - SLABS, nk & 3);  // cross-tile prefetch
      cp_commit();

      const uint32_t sb = sbase + (uint32_t)(ks & 3) * STAGE_BYTES;
#pragma unroll
      for (int kc = 0; kc < 4; ++kc) {
        uint32_t A[4][4], Bf[4][2];
        const uint32_t swA = (uint32_t)(((2 * kc + hiA) ^ l7) << 4);
        const uint32_t swB = (uint32_t)(((2 * kc + hiB) ^ l7) << 4);
#pragma unroll
        for (int mf = 0; mf < 4; ++mf)
          ldsm4(A[mf], sb + aRow + (uint32_t)mf * 2048 + swA);
#pragma unroll
        for (int nf = 0; nf < 4; ++nf)
          ldsm2(Bf[nf], sb + bRow + (uint32_t)nf * 1024 + swB);
#pragma unroll
        for (int mf = 0; mf < 4; ++mf)
#pragma unroll
          for (int j = 0; j < 4; ++j) A[mf][j] = rn_tf32(A[mf][j]);
#pragma unroll
        for (int nf = 0; nf < 4; ++nf) {
          Bf[nf][0] = rn_tf32(Bf[nf][0]);
          Bf[nf][1] = rn_tf32(Bf[nf][1]);
        }
#pragma unroll
        for (int mf = 0; mf < 4; ++mf)
#pragma unroll
          for (int nf = 0; nf < 4; ++nf) mma8(acc[mf][nf], A[mf], Bf[nf]);
      }
    }

    __syncthreads();  // all computes done; staging free (prev scan complete)

    // accum fragments -> padded staging [t][o]
#pragma unroll
    for (int mf = 0; mf < 4; ++mf)
#pragma unroll
      for (int nf = 0; nf < 4; ++nf) {
        const int r = warp_m * 64 + mf * 16 + (lane >> 2);
        const int cc = warp_n * 32 + nf * 8 + (lane & 3) * 2;
        float2 lo = {acc[mf][nf][0], acc[mf][nf][1]};
        float2 hi = {acc[mf][nf][2], acc[mf][nf][3]};
        *(float2*)&staging[r * STG_STRIDE + cc] = lo;
        *(float2*)&staging[(r + 8) * STG_STRIDE + cc] = hi;
      }
    __syncthreads();

    // fused leaky-integrator scan: carry u persists across tiles
    if (tid < 128) {
      float* ob = out + (size_t)(bb * T + t0) * OUT + o0 + tid;
#pragma unroll 4
      for (int t = 0; t < TT; ++t) {
        const float x = staging[t * STG_STRIDE + tid] + bo;
        u = fmaf(dcy, u, omd * x);
        ob[(size_t)t * OUT] = u;
      }
    }
    // next iteration's k-loop __syncthreads orders staging reuse
  }
}

}  // namespace li

extern "C" void kernel_launch(void* const* d_in, const int* in_sizes, int n_in,
                              void* d_out, int out_size) {
  const float* X = (const float*)d_in[0];      // [B,T,IN]
  const float* W = (const float*)d_in[1];      // [OUT,IN]
  const float* bias = (const float*)d_in[2];   // [OUT]
  const float* decay = (const float*)d_in[3];  // [OUT]
  float* out = (float*)d_out;                  // [B,T,OUT]

  static bool attr_set = false;
  if (!attr_set) {
    cudaFuncSetAttribute(li::li_kernel,
                         cudaFuncAttributeMaxDynamicSharedMemorySize,
                         li::SMEM_DYN);
    attr_set = true;
  }
  li::li_kernel<<<li::B * (li::OUT / li::TO), 256, li::SMEM_DYN>>>(
      X, W, bias, decay, out);
}

// round 4
// speedup vs baseline: 2.0457x; 2.0457x over previous
#include <cuda_runtime.h>
#include <cuda_fp16.h>
#include <cstdint>
#include <cstddef>

#define DEVI static __device__ __forceinline__

namespace li {

constexpr int B = 32, T = 1024, IN = 1024, OUT = 1024;
constexpr int TT = 128;                 // time rows per tile (GEMM M)
constexpr int TO = 128;                 // out cols per CTA   (GEMM N)
constexpr int BKH = 64;                 // halves per K slab (= one 128B row)
constexpr int SLABS = IN / BKH;         // 16
constexpr int TILES = T / TT;           // 8
constexpr int G = TILES * SLABS;        // 128 slabs per CTA

constexpr int STAGE_BYTES = (TT + TO) * 128;   // 32 KB (X 16K + W 16K, fp16)
constexpr int STG_STRIDE = 136;                // halves; 68 words -> 4r+q banks, conflict-free
constexpr int STAGING_OFF = 2 * STAGE_BYTES;   // 65536
constexpr int SMEM_DYN = STAGING_OFF + TT * STG_STRIDE * 2;  // 100352

__device__ __align__(16) __half g_Xh[(size_t)B * T * IN];   // 64MB scratch
__device__ __align__(16) __half g_Wh[(size_t)OUT * IN];     // 2MB scratch

DEVI uint32_t s2u(const void* p) {
  uint32_t a;
  asm("{ .reg .u64 t; cvta.to.shared.u64 t, %1; cvt.u32.u64 %0, t; }"
      : "=r"(a) : "l"(p));
  return a;
}
DEVI void cp16(uint32_t s, const void* g) {
  asm volatile("cp.async.cg.shared.global [%0], [%1], 16;" :: "r"(s), "l"(g)
               : "memory");
}
DEVI void cp_commit() { asm volatile("cp.async.commit_group;" ::: "memory"); }
DEVI void cp_wait0() { asm volatile("cp.async.wait_group 0;" ::: "memory"); }

DEVI void ldsm4(uint32_t* r, uint32_t a) {
  asm volatile("ldmatrix.sync.aligned.m8n8.x4.shared.b16 {%0,%1,%2,%3}, [%4];"
               : "=r"(r[0]), "=r"(r[1]), "=r"(r[2]), "=r"(r[3]) : "r"(a));
}
DEVI void mma16(float* c, const uint32_t* a, const uint32_t* b) {
  asm volatile(
      "mma.sync.aligned.m16n8k16.row.col.f32.f16.f16.f32 "
      "{%0,%1,%2,%3}, {%4,%5,%6,%7}, {%8,%9}, {%0,%1,%2,%3};"
      : "+f"(c[0]), "+f"(c[1]), "+f"(c[2]), "+f"(c[3])
      : "r"(a[0]), "r"(a[1]), "r"(a[2]), "r"(a[3]), "r"(b[0]), "r"(b[1]));
}
DEVI uint32_t packh2(float lo, float hi) {
  uint32_t d;
  asm("cvt.rn.f16x2.f32 %0, %1, %2;" : "=r"(d) : "f"(hi), "f"(lo));
  return d;
}

// ---------------- pre-pass: fp32 -> fp16 conversion into scratch -------------
__global__ void __launch_bounds__(256) cvt_kernel(const float4* __restrict__ X,
                                                  const float4* __restrict__ W) {
  const int64_t nx = (int64_t)B * T * IN / 4;    // 8388608
  const int64_t nw = (int64_t)OUT * IN / 4;      // 262144
  uint2* xo = reinterpret_cast<uint2*>(g_Xh);
  uint2* wo = reinterpret_cast<uint2*>(g_Wh);
  const int64_t stride = (int64_t)gridDim.x * blockDim.x;
  for (int64_t i = (int64_t)blockIdx.x * blockDim.x + threadIdx.x; i < nx;
       i += stride) {
    float4 v = X[i];
    __half2 a = __float22half2_rn({v.x, v.y});
    __half2 b = __float22half2_rn({v.z, v.w});
    uint2 u;
    u.x = *reinterpret_cast<unsigned*>(&a);
    u.y = *reinterpret_cast<unsigned*>(&b);
    xo[i] = u;
  }
  for (int64_t i = (int64_t)blockIdx.x * blockDim.x + threadIdx.x; i < nw;
       i += stride) {
    float4 v = W[i];
    __half2 a = __float22half2_rn({v.x, v.y});
    __half2 b = __float22half2_rn({v.z, v.w});
    uint2 u;
    u.x = *reinterpret_cast<unsigned*>(&a);
    u.y = *reinterpret_cast<unsigned*>(&b);
    wo[i] = u;
  }
}

// ---------------- main fused GEMM + leaky-integrator scan --------------------
__global__ void __launch_bounds__(256, 2)
li_kernel(const float* __restrict__ bias, const float* __restrict__ decay,
          float* __restrict__ out) {
  extern __shared__ __align__(16) char dsm[];
  const uint32_t sbase = s2u(dsm);
  const uint32_t stg = sbase + STAGING_OFF;

  const int tid = threadIdx.x;
  const int wid = tid >> 5;
  const int lane = tid & 31;
  const int bb = blockIdx.x >> 3;
  const int o0 = (blockIdx.x & 7) * TO;

  // ---- scan state (threads 0..127 own one o-channel) ----
  float dcy = 0.f, omd = 0.f, bo = 0.f, u = 0.f;
  if (tid < 128) {
    dcy = decay[o0 + tid];
    omd = 1.0f - dcy;
    bo = bias[o0 + tid];
  }

  // ---- cp.async constants: 8 chunks of 16B (= 8 halves) per thread ----
  const int lr = tid >> 3;   // row 0..31 (+32*i)
  const int lc = tid & 7;    // 16B chunk 0..7 within 128B row
  const uint32_t sw_off = (uint32_t)lr * 128 + (uint32_t)((lc ^ (lr & 7)) << 4);
  const __half* Wg = g_Wh + (size_t)(o0 + lr) * IN + lc * 8;
  const __half* Xg0 = g_Xh + ((size_t)bb * T + lr) * IN + lc * 8;

  // ---- mma per-thread constants ----
  const int warp_m = wid >> 2, warp_n = wid & 3;
  const int r = lane & 7;
  const int mA = lane >> 3;                    // A matrix id 0..3
  const int khA = lane >> 4;                   // A k-half select
  const int khB = (lane >> 3) & 1;             // B k-half select
  const uint32_t aBase =
      (uint32_t)(warp_m * 64 + (mA & 1) * 8 + r) * 128;
  const uint32_t bBase =
      (uint32_t)(TT * 128) +
      (uint32_t)(warp_n * 32 + ((lane >> 4) << 3) + r) * 128;

  float acc[4][4][4];

  auto load_slab = [&](int g) {
    const int t0 = (g >> 4) * TT;
    const int k0 = (g & 15) * BKH;
    const uint32_t sb = sbase + (uint32_t)(g & 1) * STAGE_BYTES;
    const __half* Xg = Xg0 + (size_t)t0 * IN + k0;
    const __half* Ws = Wg + k0;
#pragma unroll
    for (int i = 0; i < 4; ++i)
      cp16(sb + sw_off + (uint32_t)i * 4096, Xg + (size_t)i * 32 * IN);
#pragma unroll
    for (int i = 0; i < 4; ++i)
      cp16(sb + (uint32_t)(TT * 128) + sw_off + (uint32_t)i * 4096,
           Ws + (size_t)i * 32 * IN);
  };

  int g = 0;
  load_slab(0);
  cp_commit();

  for (int tile = 0; tile < TILES; ++tile) {
#pragma unroll
    for (int mf = 0; mf < 4; ++mf)
#pragma unroll
      for (int nf = 0; nf < 4; ++nf)
#pragma unroll
        for (int j = 0; j < 4; ++j) acc[mf][nf][j] = 0.f;

    for (int ks = 0; ks < SLABS; ++ks) {
      cp_wait0();
      __syncthreads();
      if (g + 1 < G) {
        load_slab(g + 1);  // overwrites the buffer computed last iteration
        cp_commit();
      }
      const uint32_t sb = sbase + (uint32_t)(g & 1) * STAGE_BYTES;
#pragma unroll
      for (int kc = 0; kc < 4; ++kc) {
        uint32_t A[4][4], Bf[2][4];
        const uint32_t swA = (uint32_t)(((2 * kc + khA) ^ r) << 4);
        const uint32_t swB = (uint32_t)(((2 * kc + khB) ^ r) << 4);
#pragma unroll
        for (int mf = 0; mf < 4; ++mf)
          ldsm4(A[mf], sb + aBase + (uint32_t)mf * 2048 + swA);
#pragma unroll
        for (int nfp = 0; nfp < 2; ++nfp)
          ldsm4(Bf[nfp], sb + bBase + (uint32_t)nfp * 2048 + swB);
#pragma unroll
        for (int mf = 0; mf < 4; ++mf)
#pragma unroll
          for (int nf = 0; nf < 4; ++nf)
            mma16(acc[mf][nf], A[mf], &Bf[nf >> 1][(nf & 1) * 2]);
      }
      ++g;
    }

    // ---- epilogue: fragments -> fp16 staging [t][o] ----
    __syncthreads();  // prev tile's scan readers done with staging
    unsigned* stg_u = reinterpret_cast<unsigned*>(dsm + STAGING_OFF);
#pragma unroll
    for (int mf = 0; mf < 4; ++mf)
#pragma unroll
      for (int nf = 0; nf < 4; ++nf) {
        const int row = warp_m * 64 + mf * 16 + (lane >> 2);
        const int col = warp_n * 32 + nf * 8 + 2 * (lane & 3);
        stg_u[(row * STG_STRIDE + col) >> 1] =
            packh2(acc[mf][nf][0], acc[mf][nf][1]);
        stg_u[((row + 8) * STG_STRIDE + col) >> 1] =
            packh2(acc[mf][nf][2], acc[mf][nf][3]);
      }
    __syncthreads();

    // ---- fused leaky-integrator scan; carry u persists across tiles ----
    if (tid < 128) {
      const __half* sh = reinterpret_cast<const __half*>(dsm + STAGING_OFF);
      float* ob = out + ((size_t)bb * T + tile * TT) * OUT + o0 + tid;
#pragma unroll 8
      for (int t = 0; t < TT; ++t) {
        const float x = __half2float(sh[t * STG_STRIDE + tid]) + bo;
        u = fmaf(dcy, u, omd * x);
        ob[(size_t)t * OUT] = u;
      }
    }
    // staging reuse ordered by next tile's epilogue-leading __syncthreads;
    // stage-buffer reuse ordered by slab loop's __syncthreads.
  }
}

}  // namespace li

extern "C" void kernel_launch(void* const* d_in, const int* in_sizes, int n_in,
                              void* d_out, int out_size) {
  const float* X = (const float*)d_in[0];      // [B,T,IN]
  const float* W = (const float*)d_in[1];      // [OUT,IN]
  const float* bias = (const float*)d_in[2];   // [OUT]
  const float* decay = (const float*)d_in[3];  // [OUT]
  float* out = (float*)d_out;                  // [B,T,OUT]

  cudaFuncSetAttribute(li::li_kernel,
                       cudaFuncAttributeMaxDynamicSharedMemorySize,
                       li::SMEM_DYN);

  li::cvt_kernel<<<2048, 256>>>((const float4*)X, (const float4*)W);
  li::li_kernel<<<li::B * (li::OUT / li::TO), 256, li::SMEM_DYN>>>(bias, decay,
                                                                   out);
}

// round 5
// speedup vs baseline: 2.0823x; 1.0179x over previous
#include <cuda_runtime.h>
#include <cuda_fp16.h>
#include <cstdint>
#include <cstddef>

#define DEVI static __device__ __forceinline__

namespace li {

constexpr int B = 32, T = 1024, IN = 1024, OUT = 1024;
constexpr int TT = 128;                 // time rows per tile (GEMM M)
constexpr int TO = 128;                 // out cols per CTA   (GEMM N)
constexpr int BKH = 64;                 // halves per K slab (= one 128B row)
constexpr int SLABS = IN / BKH;         // 16
constexpr int TILES = T / TT;           // 8
constexpr int G = TILES * SLABS;        // 128 slabs per CTA

constexpr int STAGE_BYTES = (TT + TO) * 128;   // 32 KB (X 16K + W 16K, fp16)
constexpr int STG_STRIDE = 136;                // halves; conflict-free writes
constexpr int STAGING_OFF = 2 * STAGE_BYTES;   // 65536
constexpr int SMEM_DYN = STAGING_OFF + TT * STG_STRIDE * 2;  // 100352

__device__ __align__(16) __half g_Xh[(size_t)B * T * IN];   // 64MB scratch
__device__ __align__(16) __half g_Wh[(size_t)OUT * IN];     // 2MB scratch

DEVI uint32_t s2u(const void* p) {
  uint32_t a;
  asm("{ .reg .u64 t; cvta.to.shared.u64 t, %1; cvt.u32.u64 %0, t; }"
      : "=r"(a) : "l"(p));
  return a;
}
DEVI void cp16(uint32_t s, const void* g) {
  asm volatile("cp.async.cg.shared.global [%0], [%1], 16;" :: "r"(s), "l"(g)
               : "memory");
}
DEVI void cp_commit() { asm volatile("cp.async.commit_group;" ::: "memory"); }
DEVI void cp_wait0() { asm volatile("cp.async.wait_group 0;" ::: "memory"); }

DEVI void ldsm4(uint32_t* r, uint32_t a) {
  asm volatile("ldmatrix.sync.aligned.m8n8.x4.shared.b16 {%0,%1,%2,%3}, [%4];"
               : "=r"(r[0]), "=r"(r[1]), "=r"(r[2]), "=r"(r[3]) : "r"(a));
}
DEVI void mma16(float* c, const uint32_t* a, const uint32_t* b) {
  asm volatile(
      "mma.sync.aligned.m16n8k16.row.col.f32.f16.f16.f32 "
      "{%0,%1,%2,%3}, {%4,%5,%6,%7}, {%8,%9}, {%0,%1,%2,%3};"
      : "+f"(c[0]), "+f"(c[1]), "+f"(c[2]), "+f"(c[3])
      : "r"(a[0]), "r"(a[1]), "r"(a[2]), "r"(a[3]), "r"(b[0]), "r"(b[1]));
}
DEVI uint32_t packh2(float lo, float hi) {
  uint32_t d;
  asm("cvt.rn.f16x2.f32 %0, %1, %2;" : "=r"(d) : "f"(hi), "f"(lo));
  return d;
}

// ---------------- pre-pass: fp32 -> fp16 conversion into scratch -------------
__global__ void __launch_bounds__(256) cvt_kernel(const float4* __restrict__ X,
                                                  const float4* __restrict__ W) {
  const int64_t nx = (int64_t)B * T * IN / 4;
  const int64_t nw = (int64_t)OUT * IN / 4;
  uint2* xo = reinterpret_cast<uint2*>(g_Xh);
  uint2* wo = reinterpret_cast<uint2*>(g_Wh);
  const int64_t stride = (int64_t)gridDim.x * blockDim.x;
  for (int64_t i = (int64_t)blockIdx.x * blockDim.x + threadIdx.x; i < nx;
       i += stride) {
    float4 v = X[i];
    __half2 a = __float22half2_rn({v.x, v.y});
    __half2 b = __float22half2_rn({v.z, v.w});
    uint2 u;
    u.x = *reinterpret_cast<unsigned*>(&a);
    u.y = *reinterpret_cast<unsigned*>(&b);
    xo[i] = u;
  }
  for (int64_t i = (int64_t)blockIdx.x * blockDim.x + threadIdx.x; i < nw;
       i += stride) {
    float4 v = W[i];
    __half2 a = __float22half2_rn({v.x, v.y});
    __half2 b = __float22half2_rn({v.z, v.w});
    uint2 u;
    u.x = *reinterpret_cast<unsigned*>(&a);
    u.y = *reinterpret_cast<unsigned*>(&b);
    wo[i] = u;
  }
}

// ---------------- main fused GEMM + leaky-integrator scan --------------------
// 128 threads, 4 warps in 2x2 grid, warp tile 64x64.
__global__ void __launch_bounds__(128, 2)
li_kernel(const float* __restrict__ bias, const float* __restrict__ decay,
          float* __restrict__ out) {
  extern __shared__ __align__(16) char dsm[];
  const uint32_t sbase = s2u(dsm);

  const int tid = threadIdx.x;
  const int wid = tid >> 5;
  const int lane = tid & 31;
  const int bb = blockIdx.x >> 3;
  const int o0 = (blockIdx.x & 7) * TO;

  // ---- scan state: every thread owns one o-channel ----
  const float dcy = decay[o0 + tid];
  const float omd = 1.0f - dcy;
  const float bo = bias[o0 + tid];
  float u = 0.f;

  // ---- cp.async constants: 16 chunks of 16B per thread ----
  const int lr = tid >> 3;   // row 0..15 (+16*i)
  const int lc = tid & 7;    // 16B chunk within 128B row
  const uint32_t sw_off = (uint32_t)lr * 128 + (uint32_t)((lc ^ (lr & 7)) << 4);
  const __half* Wg = g_Wh + (size_t)(o0 + lr) * IN + lc * 8;
  const __half* Xg0 = g_Xh + ((size_t)bb * T + lr) * IN + lc * 8;

  // ---- mma per-thread constants ----
  const int warp_m = wid >> 1, warp_n = wid & 1;
  const int r = lane & 7;
  const int khA = lane >> 4;
  const int khB = (lane >> 3) & 1;
  const uint32_t aBase =
      (uint32_t)(warp_m * 64 + ((lane >> 3) & 1) * 8 + r) * 128;
  const uint32_t bBase =
      (uint32_t)(TT * 128) +
      (uint32_t)(warp_n * 64 + ((lane >> 4) << 3) + r) * 128;

  float acc[4][8][4];

  auto load_slab = [&](int g) {
    const int t0 = (g >> 4) * TT;
    const int k0 = (g & 15) * BKH;
    const uint32_t sb = sbase + (uint32_t)(g & 1) * STAGE_BYTES;
    const __half* Xg = Xg0 + (size_t)t0 * IN + k0;
    const __half* Ws = Wg + k0;
#pragma unroll
    for (int i = 0; i < 8; ++i)
      cp16(sb + sw_off + (uint32_t)i * 2048, Xg + (size_t)i * 16 * IN);
#pragma unroll
    for (int i = 0; i < 8; ++i)
      cp16(sb + (uint32_t)(TT * 128) + sw_off + (uint32_t)i * 2048,
           Ws + (size_t)i * 16 * IN);
  };

  int g = 0;
  load_slab(0);
  cp_commit();

  for (int tile = 0; tile < TILES; ++tile) {
#pragma unroll
    for (int mf = 0; mf < 4; ++mf)
#pragma unroll
      for (int nf = 0; nf < 8; ++nf)
#pragma unroll
        for (int j = 0; j < 4; ++j) acc[mf][nf][j] = 0.f;

    for (int ks = 0; ks < SLABS; ++ks) {
      cp_wait0();
      __syncthreads();
      if (g + 1 < G) {
        load_slab(g + 1);  // into the buffer consumed last iteration
        cp_commit();
      }
      const uint32_t sb = sbase + (uint32_t)(g & 1) * STAGE_BYTES;
#pragma unroll
      for (int kc = 0; kc < 4; ++kc) {
        uint32_t A[4][4], Bf[4][4];
        const uint32_t swA = (uint32_t)(((2 * kc + khA) ^ r) << 4);
        const uint32_t swB = (uint32_t)(((2 * kc + khB) ^ r) << 4);
#pragma unroll
        for (int mf = 0; mf < 4; ++mf)
          ldsm4(A[mf], sb + aBase + (uint32_t)mf * 2048 + swA);
#pragma unroll
        for (int p = 0; p < 4; ++p)
          ldsm4(Bf[p], sb + bBase + (uint32_t)p * 2048 + swB);
#pragma unroll
        for (int mf = 0; mf < 4; ++mf)
#pragma unroll
          for (int nf = 0; nf < 8; ++nf)
            mma16(acc[mf][nf], A[mf], &Bf[nf >> 1][(nf & 1) * 2]);
      }
      ++g;
    }

    // ---- epilogue: fragments -> fp16 staging [t][o] ----
    // (ordered vs previous tile's scan by the 16 slab-loop barriers)
    unsigned* stg_u = reinterpret_cast<unsigned*>(dsm + STAGING_OFF);
#pragma unroll
    for (int mf = 0; mf < 4; ++mf)
#pragma unroll
      for (int nf = 0; nf < 8; ++nf) {
        const int row = warp_m * 64 + mf * 16 + (lane >> 2);
        const int col = warp_n * 64 + nf * 8 + 2 * (lane & 3);
        stg_u[(row * STG_STRIDE + col) >> 1] =
            packh2(acc[mf][nf][0], acc[mf][nf][1]);
        stg_u[((row + 8) * STG_STRIDE + col) >> 1] =
            packh2(acc[mf][nf][2], acc[mf][nf][3]);
      }
    __syncthreads();

    // ---- fused leaky-integrator scan; carry u persists across tiles ----
    {
      const __half* sh = reinterpret_cast<const __half*>(dsm + STAGING_OFF);
      float* ob = out + ((size_t)bb * T + tile * TT) * OUT + o0 + tid;
#pragma unroll 8
      for (int t = 0; t < TT; ++t) {
        const float x = __half2float(sh[t * STG_STRIDE + tid]) + bo;
        u = fmaf(dcy, u, omd * x);
        ob[(size_t)t * OUT] = u;
      }
    }
  }
}

}  // namespace li

extern "C" void kernel_launch(void* const* d_in, const int* in_sizes, int n_in,
                              void* d_out, int out_size) {
  const float* X = (const float*)d_in[0];      // [B,T,IN]
  const float* W = (const float*)d_in[1];      // [OUT,IN]
  const float* bias = (const float*)d_in[2];   // [OUT]
  const float* decay = (const float*)d_in[3];  // [OUT]
  float* out = (float*)d_out;                  // [B,T,OUT]

  cudaFuncSetAttribute(li::li_kernel,
                       cudaFuncAttributeMaxDynamicSharedMemorySize,
                       li::SMEM_DYN);

  li::cvt_kernel<<<1184, 256>>>((const float4*)X, (const float4*)W);
  li::li_kernel<<<li::B * (li::OUT / li::TO), 128, li::SMEM_DYN>>>(bias, decay,
                                                                   out);
}